// round 1
// baseline (speedup 1.0000x reference)
#include <cuda_runtime.h>
#include <math.h>

#define NB   64
#define NN   512
#define NC   128
#define NFS  16
#define NRES 511
#define NBN  (NB*NN)

// Scratch (no allocations allowed)
__device__ float g_score[NBN];
__device__ float g_ssrc[NBN];
__device__ float g_sdst[NBN];
__device__ int   g_order[NBN];
__device__ float g_sr[NBN];
__device__ float g_dsrc[NBN];
__device__ float g_ddst[NBN];
__device__ float g_wv[NB*NRES];
__device__ int   g_jumps[NB*NRES];

// -------- Kernel 1: per-node score + attention dots (warp per node) --------
__global__ void k_scores(const float* __restrict__ x,
                         const float* __restrict__ sw,
                         const float* __restrict__ ap) {
    int gw   = (blockIdx.x * blockDim.x + threadIdx.x) >> 5;
    int lane = threadIdx.x & 31;
    if (gw >= NBN) return;
    float4 xv = *(const float4*)(x  + (size_t)gw * NC + lane * 4);
    float4 wv = *(const float4*)(sw + lane * 4);
    float4 as = *(const float4*)(ap + lane * 4);
    float4 ad = *(const float4*)(ap + NC + lane * 4);
    float s  = xv.x*wv.x + xv.y*wv.y + xv.z*wv.z + xv.w*wv.w;
    float ps = xv.x*as.x + xv.y*as.y + xv.z*as.z + xv.w*as.w;
    float pd = xv.x*ad.x + xv.y*ad.y + xv.z*ad.z + xv.w*ad.w;
    float wn = wv.x*wv.x + wv.y*wv.y + wv.z*wv.z + wv.w*wv.w;
    #pragma unroll
    for (int o = 16; o; o >>= 1) {
        s  += __shfl_xor_sync(0xffffffffu, s,  o);
        ps += __shfl_xor_sync(0xffffffffu, ps, o);
        pd += __shfl_xor_sync(0xffffffffu, pd, o);
        wn += __shfl_xor_sync(0xffffffffu, wn, o);
    }
    if (lane == 0) {
        g_score[gw] = s / sqrtf(wn);
        g_ssrc[gw]  = ps;
        g_sdst[gw]  = pd;
    }
}

// -------- Kernel 2: per-batch bitonic sort (desc score, asc index) --------
__device__ __forceinline__ bool before_desc(float a_s, int a_i, float b_s, int b_i) {
    // true if (a_s, a_i) should precede (b_s, b_i) in descending-score order
    return (a_s > b_s) || (a_s == b_s && a_i < b_i);
}

__global__ void k_sort() {
    __shared__ float ss[NN];
    __shared__ int   si[NN];
    int b = blockIdx.x, t = threadIdx.x;
    ss[t] = g_score[b * NN + t];
    si[t] = t;
    __syncthreads();
    for (int k = 2; k <= NN; k <<= 1) {
        for (int j = k >> 1; j > 0; j >>= 1) {
            int l = t ^ j;
            if (l > t) {
                float a = ss[t], c = ss[l];
                int   ia = si[t], ic = si[l];
                bool up = ((t & k) == 0);
                bool sw = up ? before_desc(c, ic, a, ia)
                             : before_desc(a, ia, c, ic);
                if (sw) { ss[t] = c; ss[l] = a; si[t] = ic; si[l] = ia; }
            }
            __syncthreads();
        }
    }
    int gi = b * NN + si[t];
    g_order[b * NN + t] = si[t];
    g_sr[b * NN + t]    = tanhf(ss[t]);
    g_dsrc[b * NN + t]  = g_ssrc[gi];
    g_ddst[b * NN + t]  = g_sdst[gi];
}

// -------- Kernel 3: banded window -> w_row*sr and jumps (warp per r) --------
__global__ void k_windows(const float* __restrict__ x,
                          const int*   __restrict__ ep) {
    int b    = blockIdx.y;
    int r    = blockIdx.x * 8 + (threadIdx.x >> 5);
    int lane = threadIdx.x & 31;
    if (r >= NRES) return;

    int epoch = *ep;
    // tau0 = 10 * (0.1/10)^(epoch/100) = 10 * exp(epoch * ln(0.01)/100)
    float tau = (float)(10.0 * exp((double)epoch * -0.046051701859880914));

    const int* ord = g_order + b * NN;
    int   i0 = ord[r];
    float4 xs = *(const float4*)(x + ((size_t)(b * NN + i0)) * NC + lane * 4);
    float dsr = g_dsrc[b * NN + r];

    float att[16], kk[16];
    // j = 0: dest == src -> d = 0 -> k = exp(0) - EPS = 1
    kk[0]  = 1.0f;
    att[0] = dsr + g_ddst[b * NN + r];

    #pragma unroll
    for (int j = 1; j < NFS; j++) {
        int dest   = r + j;
        bool valid = dest < NN;
        int destc  = valid ? dest : (NN - 1);
        int id     = ord[destc];
        float4 xd  = *(const float4*)(x + ((size_t)(b * NN + id)) * NC + lane * 4);
        float dx = xs.x - xd.x, dy = xs.y - xd.y, dz = xs.z - xd.z, dw = xs.w - xd.w;
        float d2 = dx*dx + dy*dy + dz*dz + dw*dw;
        #pragma unroll
        for (int o = 16; o; o >>= 1) d2 += __shfl_xor_sync(0xffffffffu, d2, o);
        float d = sqrtf(d2);
        kk[j]  = valid ? (expf(-0.5f * d) - 1e-20f) : -1e-20f;
        att[j] = valid ? (dsr + g_ddst[b * NN + destc]) : -1e9f;
    }

    // softmax(att / tau)
    float m = att[0];
    #pragma unroll
    for (int j = 1; j < NFS; j++) m = fmaxf(m, att[j]);
    float e[16], ssum = 0.0f;
    #pragma unroll
    for (int j = 0; j < NFS; j++) { e[j] = expf((att[j] - m) / tau); ssum += e[j]; }
    float inv = 1.0f / ssum;

    float wrow = -1e9f;
    float best = -3e9f;
    int   bj   = 1;
    #pragma unroll
    for (int j = 0; j < NFS; j++) {
        bool valid = (r + j) < NN;
        float q  = kk[j] * (e[j] * inv);
        float qm = valid ? q : -1e9f;
        wrow = fmaxf(wrow, qm);
        if (j >= 1 && qm > best) { best = qm; bj = j; }  // first-max semantics
    }

    if (lane == 0) {
        g_wv[b * NRES + r]    = wrow * g_sr[b * NN + r];
        g_jumps[b * NRES + r] = bj;
    }
}

// -------- Kernel 4: serial jump-chain accumulation (block per batch) --------
__global__ void k_chain(const float* __restrict__ x, float* __restrict__ out) {
    __shared__ float swv[NRES];
    __shared__ int   sj[NRES];
    __shared__ int   sord[NRES];
    int b = blockIdx.x, t = threadIdx.x;  // 128 threads = channels
    for (int i = t; i < NRES; i += NC) {
        swv[i]  = g_wv[b * NRES + i];
        sj[i]   = g_jumps[b * NRES + i];
        sord[i] = g_order[b * NN + i];
    }
    __syncthreads();
    float acc = 0.0f;
    int p = 0;
    while (p < NRES) {
        float w = swv[p];
        int  id = sord[p];
        acc += w * x[((size_t)(b * NN + id)) * NC + t];
        p += sj[p];
    }
    out[b * NC + t] = acc;
}

extern "C" void kernel_launch(void* const* d_in, const int* in_sizes, int n_in,
                              void* d_out, int out_size) {
    const float* x   = (const float*)d_in[0];
    // d_in[1] = edge_index (unused by the reference forward pass)
    const float* sw  = (const float*)d_in[2];
    const float* ap  = (const float*)d_in[3];
    const int*   ep  = (const int*)d_in[4];
    float* out = (float*)d_out;

    k_scores<<<NBN / 8, 256>>>(x, sw, ap);
    k_sort<<<NB, NN>>>();
    dim3 gw((NRES + 7) / 8, NB);
    k_windows<<<gw, 256>>>(x, ep);
    k_chain<<<NB, NC>>>(x, out);
}

// round 2
// speedup vs baseline: 1.2950x; 1.2950x over previous
#include <cuda_runtime.h>
#include <math.h>

#define NB   64
#define NN   512
#define NC   128
#define NFS  16
#define NRES 511
#define NBN  (NB*NN)
#define TR   32
#define TROWS (TR + NFS - 1)   // 47 tile rows

// Scratch (no allocations allowed)
__device__ float g_score[NBN];
__device__ float g_ssrc[NBN];
__device__ float g_sdst[NBN];
__device__ int   g_order[NBN];
__device__ float g_sr[NBN];
__device__ float g_dsrc[NBN];
__device__ float g_ddst[NBN];
__device__ float g_wv[NB*NRES];
__device__ int   g_jumps[NB*NRES];

// -------- Kernel 1: per-node score + attention dots (warp per node) --------
__global__ void k_scores(const float* __restrict__ x,
                         const float* __restrict__ sw,
                         const float* __restrict__ ap) {
    int gw   = (blockIdx.x * blockDim.x + threadIdx.x) >> 5;
    int lane = threadIdx.x & 31;
    if (gw >= NBN) return;
    float4 xv = *(const float4*)(x  + (size_t)gw * NC + lane * 4);
    float4 wv = *(const float4*)(sw + lane * 4);
    float4 as = *(const float4*)(ap + lane * 4);
    float4 ad = *(const float4*)(ap + NC + lane * 4);
    float s  = xv.x*wv.x + xv.y*wv.y + xv.z*wv.z + xv.w*wv.w;
    float ps = xv.x*as.x + xv.y*as.y + xv.z*as.z + xv.w*as.w;
    float pd = xv.x*ad.x + xv.y*ad.y + xv.z*ad.z + xv.w*ad.w;
    float wn = wv.x*wv.x + wv.y*wv.y + wv.z*wv.z + wv.w*wv.w;
    #pragma unroll
    for (int o = 16; o; o >>= 1) {
        s  += __shfl_xor_sync(0xffffffffu, s,  o);
        ps += __shfl_xor_sync(0xffffffffu, ps, o);
        pd += __shfl_xor_sync(0xffffffffu, pd, o);
        wn += __shfl_xor_sync(0xffffffffu, wn, o);
    }
    if (lane == 0) {
        g_score[gw] = s / sqrtf(wn);
        g_ssrc[gw]  = ps;
        g_sdst[gw]  = pd;
    }
}

// -------- Kernel 2: per-batch bitonic sort (desc score, asc index) --------
__device__ __forceinline__ bool before_desc(float a_s, int a_i, float b_s, int b_i) {
    return (a_s > b_s) || (a_s == b_s && a_i < b_i);
}

__global__ void k_sort() {
    __shared__ float ss[NN];
    __shared__ int   si[NN];
    int b = blockIdx.x, t = threadIdx.x;
    ss[t] = g_score[b * NN + t];
    si[t] = t;
    __syncthreads();
    for (int k = 2; k <= NN; k <<= 1) {
        for (int j = k >> 1; j > 0; j >>= 1) {
            int l = t ^ j;
            if (l > t) {
                float a = ss[t], c = ss[l];
                int   ia = si[t], ic = si[l];
                bool up = ((t & k) == 0);
                bool sw = up ? before_desc(c, ic, a, ia)
                             : before_desc(a, ia, c, ic);
                if (sw) { ss[t] = c; ss[l] = a; si[t] = ic; si[l] = ia; }
            }
            __syncthreads();
        }
    }
    int gi = b * NN + si[t];
    g_order[b * NN + t] = si[t];
    g_sr[b * NN + t]    = tanhf(ss[t]);
    g_dsrc[b * NN + t]  = g_ssrc[gi];
    g_ddst[b * NN + t]  = g_sdst[gi];
}

// -------- Kernel 3: tiled banded window -> w_row*sr and jumps --------
// Block: 256 threads (8 warps), handles TR=32 consecutive r for one batch.
// Stages the 47 gathered rows into SMEM once; each warp computes 4 rows.
__global__ void k_windows(const float* __restrict__ x,
                          const int*   __restrict__ ep) {
    __shared__ float tile[TROWS * NC];   // 24064 B
    __shared__ float sddst[TROWS];
    int b  = blockIdx.y;
    int r0 = blockIdx.x * TR;
    int t = threadIdx.x, w = t >> 5, lane = t & 31;
    const int* ord = g_order + b * NN;

    // stage gathered x rows (clamped) into SMEM
    for (int rr = w; rr < TROWS; rr += 8) {
        int gr  = r0 + rr;
        int grc = gr < NN ? gr : (NN - 1);
        int id  = ord[grc];
        float4 v = *(const float4*)(x + ((size_t)(b * NN + id)) * NC + lane * 4);
        *(float4*)(tile + rr * NC + lane * 4) = v;
    }
    if (t < TROWS) {
        int gr  = r0 + t;
        int grc = gr < NN ? gr : (NN - 1);
        sddst[t] = g_ddst[b * NN + grc];
    }
    __syncthreads();

    int epoch = *ep;
    float tau = (float)(10.0 * exp((double)epoch * -0.046051701859880914));

    #pragma unroll
    for (int kk_r = 0; kk_r < 4; kk_r++) {
        int rl = w + kk_r * 8;
        int r  = r0 + rl;
        if (r >= NRES) continue;

        float4 xs = *(const float4*)(tile + rl * NC + lane * 4);
        float dsr = g_dsrc[b * NN + r];

        float att[16], kk[16];
        kk[0]  = 1.0f;                 // j=0: d=0 -> exp(0)-EPS ~= 1
        att[0] = dsr + sddst[rl];

        #pragma unroll
        for (int j = 1; j < NFS; j++) {
            bool valid = (r + j) < NN;
            float4 xd = *(const float4*)(tile + (rl + j) * NC + lane * 4);
            float dx = xs.x - xd.x, dy = xs.y - xd.y, dz = xs.z - xd.z, dw = xs.w - xd.w;
            float d2 = dx*dx + dy*dy + dz*dz + dw*dw;
            #pragma unroll
            for (int o = 16; o; o >>= 1) d2 += __shfl_xor_sync(0xffffffffu, d2, o);
            kk[j]  = valid ? (expf(-0.5f * sqrtf(d2)) - 1e-20f) : -1e-20f;
            att[j] = valid ? (dsr + sddst[rl + j]) : -1e9f;
        }

        float m = att[0];
        #pragma unroll
        for (int j = 1; j < NFS; j++) m = fmaxf(m, att[j]);
        float e[16], ssum = 0.0f;
        #pragma unroll
        for (int j = 0; j < NFS; j++) { e[j] = expf((att[j] - m) / tau); ssum += e[j]; }
        float inv = 1.0f / ssum;

        float wrow = -1e9f;
        float best = -3e9f;
        int   bj   = 1;
        #pragma unroll
        for (int j = 0; j < NFS; j++) {
            bool valid = (r + j) < NN;
            float q  = kk[j] * (e[j] * inv);
            float qm = valid ? q : -1e9f;
            wrow = fmaxf(wrow, qm);
            if (j >= 1 && qm > best) { best = qm; bj = j; }
        }

        if (lane == 0) {
            g_wv[b * NRES + r]    = wrow * g_sr[b * NN + r];
            g_jumps[b * NRES + r] = bj;
        }
    }
}

// -------- Kernel 4: path-first chain, then parallel accumulation --------
__global__ void k_chain(const float* __restrict__ x, float* __restrict__ out) {
    __shared__ float swv[NRES];
    __shared__ int   sj[NRES];
    __shared__ int   sord[NRES];
    __shared__ int   spath[NRES];
    __shared__ float swt[NRES];
    __shared__ int   scount;
    int b = blockIdx.x, t = threadIdx.x;   // 128 threads = channels
    for (int i = t; i < NRES; i += NC) {
        swv[i]  = g_wv[b * NRES + i];
        sj[i]   = g_jumps[b * NRES + i];
        sord[i] = g_order[b * NN + i];
    }
    __syncthreads();

    if (t == 0) {    // serial pointer-chase through SMEM only (~30 cyc/step)
        int p = 0, n = 0;
        while (p < NRES) {
            spath[n] = sord[p];
            swt[n]   = swv[p];
            n++;
            p += sj[p];
        }
        scount = n;
    }
    __syncthreads();

    int n = scount;
    const float* xb = x + (size_t)b * NN * NC;
    float acc = 0.0f;
    int i = 0;
    for (; i + 4 <= n; i += 4) {   // independent loads -> MLP 4
        float a0 = xb[(size_t)spath[i]     * NC + t];
        float a1 = xb[(size_t)spath[i + 1] * NC + t];
        float a2 = xb[(size_t)spath[i + 2] * NC + t];
        float a3 = xb[(size_t)spath[i + 3] * NC + t];
        acc += swt[i] * a0 + swt[i+1] * a1 + swt[i+2] * a2 + swt[i+3] * a3;
    }
    for (; i < n; i++)
        acc += swt[i] * xb[(size_t)spath[i] * NC + t];
    out[b * NC + t] = acc;
}

extern "C" void kernel_launch(void* const* d_in, const int* in_sizes, int n_in,
                              void* d_out, int out_size) {
    const float* x   = (const float*)d_in[0];
    // d_in[1] = edge_index (unused by the reference forward pass)
    const float* sw  = (const float*)d_in[2];
    const float* ap  = (const float*)d_in[3];
    const int*   ep  = (const int*)d_in[4];
    float* out = (float*)d_out;

    k_scores<<<NBN / 8, 256>>>(x, sw, ap);
    k_sort<<<NB, NN>>>();
    dim3 gw((NRES + TR - 1) / TR, NB);
    k_windows<<<gw, 256>>>(x, ep);
    k_chain<<<NB, NC>>>(x, out);
}

// round 4
// speedup vs baseline: 2.3443x; 1.8103x over previous
#include <cuda_runtime.h>
#include <math.h>

#define NB   64
#define NN   512
#define NC   128
#define NFS  16
#define NRES 511
#define NBN  (NB*NN)
#define TR   32
#define TROWS (TR + NFS - 1)   // 47 tile rows

// Scratch (no allocations allowed)
__device__ float g_score[NBN];
__device__ float g_ssrc[NBN];
__device__ float g_sdst[NBN];
__device__ int   g_order[NBN];
__device__ float g_sr[NBN];
__device__ float g_dsrc[NBN];
__device__ float g_ddst[NBN];
__device__ float g_wv[NB*NRES];
__device__ int   g_jumps[NB*NRES];

// -------- Kernel 1: per-node score + attention dots (warp per node) --------
__global__ void k_scores(const float* __restrict__ x,
                         const float* __restrict__ sw,
                         const float* __restrict__ ap) {
    int gw   = (blockIdx.x * blockDim.x + threadIdx.x) >> 5;
    int lane = threadIdx.x & 31;
    if (gw >= NBN) return;
    float4 xv = *(const float4*)(x  + (size_t)gw * NC + lane * 4);
    float4 wv = *(const float4*)(sw + lane * 4);
    float4 as = *(const float4*)(ap + lane * 4);
    float4 ad = *(const float4*)(ap + NC + lane * 4);
    float s  = xv.x*wv.x + xv.y*wv.y + xv.z*wv.z + xv.w*wv.w;
    float ps = xv.x*as.x + xv.y*as.y + xv.z*as.z + xv.w*as.w;
    float pd = xv.x*ad.x + xv.y*ad.y + xv.z*ad.z + xv.w*ad.w;
    float wn = wv.x*wv.x + wv.y*wv.y + wv.z*wv.z + wv.w*wv.w;
    #pragma unroll
    for (int o = 16; o; o >>= 1) {
        s  += __shfl_xor_sync(0xffffffffu, s,  o);
        ps += __shfl_xor_sync(0xffffffffu, ps, o);
        pd += __shfl_xor_sync(0xffffffffu, pd, o);
        wn += __shfl_xor_sync(0xffffffffu, wn, o);
    }
    if (lane == 0) {
        g_score[gw] = s / sqrtf(wn);
        g_ssrc[gw]  = ps;
        g_sdst[gw]  = pd;
    }
}

// -------- Kernel 2: register-resident bitonic sort with u64 keys --------
// key = (~orderedFloat(score)) << 32 | index  -> ascending u64 sort gives
// descending score, ties broken by ascending index (matches stable argsort(-s)).
__global__ void k_sort() {
    __shared__ unsigned long long sk[NN];
    int b = blockIdx.x, t = threadIdx.x;
    float sval = g_score[b * NN + t];
    unsigned u = __float_as_uint(sval);
    u = (u & 0x80000000u) ? ~u : (u | 0x80000000u);   // monotone-increasing map
    u = ~u;                                            // descending
    unsigned long long key = ((unsigned long long)u << 32) | (unsigned)t;

    #pragma unroll
    for (int k = 2; k <= NN; k <<= 1) {
        #pragma unroll
        for (int j = k >> 1; j > 0; j >>= 1) {
            unsigned long long other;
            if (j >= 32) {
                __syncthreads();
                sk[t] = key;
                __syncthreads();
                other = sk[t ^ j];
            } else {
                other = __shfl_xor_sync(0xffffffffu, key, j);
            }
            bool takeMin = (((t & j) == 0) == ((t & k) == 0));
            bool less = key < other;
            key = (takeMin == less) ? key : other;
        }
    }

    int idx = (int)(key & 0xffffffffu);
    int gi  = b * NN + idx;
    g_order[b * NN + t] = idx;
    g_sr[b * NN + t]    = tanhf(g_score[gi]);
    g_dsrc[b * NN + t]  = g_ssrc[gi];
    g_ddst[b * NN + t]  = g_sdst[gi];
}

// -------- Kernel 3: tiled banded window, two-phase --------
// Phase A: warps compute banded d^2 into SMEM (independent butterfly reduces).
// Phase B: threads cover all 480 (r,j) exp/sqrt; thread-per-r softmax.
__global__ void k_windows(const float* __restrict__ x,
                          const int*   __restrict__ ep) {
    __shared__ float tile[TROWS * NC];    // 24064 B
    __shared__ float sddst[TROWS];
    __shared__ float sd2[TR * 15];        // d^2 then kk, in place
    int b  = blockIdx.y;
    int r0 = blockIdx.x * TR;
    int t = threadIdx.x, w = t >> 5, lane = t & 31;
    const int* ord = g_order + b * NN;

    // stage gathered x rows (clamped) into SMEM
    for (int rr = w; rr < TROWS; rr += 8) {
        int gr  = r0 + rr;
        int grc = gr < NN ? gr : (NN - 1);
        int id  = ord[grc];
        float4 v = *(const float4*)(x + ((size_t)(b * NN + id)) * NC + lane * 4);
        *(float4*)(tile + rr * NC + lane * 4) = v;
    }
    if (t < TROWS) {
        int gr  = r0 + t;
        int grc = gr < NN ? gr : (NN - 1);
        sddst[t] = g_ddst[b * NN + grc];
    }
    __syncthreads();

    // Phase A: each warp handles rl = w, w+8, w+16, w+24
    #pragma unroll
    for (int rep = 0; rep < 4; rep++) {
        int rl = w + rep * 8;
        float4 xs = *(const float4*)(tile + rl * NC + lane * 4);
        float p[15];
        #pragma unroll
        for (int j = 1; j < NFS; j++) {
            float4 xd = *(const float4*)(tile + (rl + j) * NC + lane * 4);
            float dx = xs.x - xd.x, dy = xs.y - xd.y, dz = xs.z - xd.z, dw = xs.w - xd.w;
            p[j - 1] = dx*dx + dy*dy + dz*dz + dw*dw;
        }
        #pragma unroll
        for (int o = 16; o; o >>= 1) {
            #pragma unroll
            for (int j = 0; j < 15; j++)
                p[j] += __shfl_xor_sync(0xffffffffu, p[j], o);
        }
        if (lane == 0) {
            #pragma unroll
            for (int j = 0; j < 15; j++) sd2[rl * 15 + j] = p[j];
        }
    }
    __syncthreads();

    // Phase B1: kk = exp(-sqrt(d2)/2) - EPS for ALL 480 pairs (grid-stride!)
    for (int i = t; i < TR * 15; i += 256) {
        int rl = i / 15, jm1 = i - rl * 15;
        int r  = r0 + rl;
        bool valid = (r + jm1 + 1) < NN;
        float d2 = sd2[i];
        sd2[i] = valid ? (expf(-0.5f * sqrtf(d2)) - 1e-20f) : -1e-20f;
    }
    __syncthreads();

    // Phase B2: thread-per-r softmax / max / argmax
    if (t < TR) {
        int r = r0 + t;
        if (r < NRES) {
            int epoch = *ep;
            float tau = (float)(10.0 * exp((double)epoch * -0.046051701859880914));
            float dsr = g_dsrc[b * NN + r];

            float att[16], kk[16];
            kk[0]  = 1.0f;
            att[0] = dsr + sddst[t];
            #pragma unroll
            for (int j = 1; j < NFS; j++) {
                bool valid = (r + j) < NN;
                kk[j]  = sd2[t * 15 + (j - 1)];
                att[j] = valid ? (dsr + sddst[t + j]) : -1e9f;
            }
            float m = att[0];
            #pragma unroll
            for (int j = 1; j < NFS; j++) m = fmaxf(m, att[j]);
            float e[16], ssum = 0.0f;
            #pragma unroll
            for (int j = 0; j < NFS; j++) { e[j] = expf((att[j] - m) / tau); ssum += e[j]; }
            float inv = 1.0f / ssum;

            float wrow = -1e9f, best = -3e9f;
            int bj = 1;
            #pragma unroll
            for (int j = 0; j < NFS; j++) {
                bool valid = (r + j) < NN;
                float q  = kk[j] * (e[j] * inv);
                float qm = valid ? q : -1e9f;
                wrow = fmaxf(wrow, qm);
                if (j >= 1 && qm > best) { best = qm; bj = j; }
            }
            g_wv[b * NRES + r]    = wrow * g_sr[b * NN + r];
            g_jumps[b * NRES + r] = bj;
        }
    }
}

// -------- Kernel 4: path-first chain + 4-way split accumulation --------
__global__ void k_chain(const float* __restrict__ x, float* __restrict__ out) {
    __shared__ float swv[NRES];
    __shared__ int   sj[NRES];
    __shared__ int   sord[NRES];
    __shared__ int   spath[NRES];
    __shared__ float swt[NRES];
    __shared__ int   scount;
    __shared__ float part[4][NC];
    int b = blockIdx.x, t = threadIdx.x;   // 512 threads
    if (t < NRES) {
        swv[t]  = g_wv[b * NRES + t];
        sj[t]   = g_jumps[b * NRES + t];
        sord[t] = g_order[b * NN + t];
    }
    __syncthreads();

    if (t == 0) {     // serial pointer-chase entirely in SMEM
        int p = 0, n = 0;
        while (p < NRES) {
            spath[n] = sord[p];
            swt[n]   = swv[p];
            n++;
            p += sj[p];
        }
        scount = n;
    }
    __syncthreads();

    int n = scount;
    int c = t & (NC - 1), s = t >> 7;      // 4 replicas x 128 channels
    const float* xb = x + (size_t)b * NN * NC;
    float acc = 0.0f;
    #pragma unroll 4
    for (int i = s; i < n; i += 4)
        acc += swt[i] * xb[(size_t)spath[i] * NC + c];
    part[s][c] = acc;
    __syncthreads();
    if (s == 0)
        out[b * NC + c] = (part[0][c] + part[1][c]) + (part[2][c] + part[3][c]);
}

extern "C" void kernel_launch(void* const* d_in, const int* in_sizes, int n_in,
                              void* d_out, int out_size) {
    const float* x   = (const float*)d_in[0];
    // d_in[1] = edge_index (unused by the reference forward pass)
    const float* sw  = (const float*)d_in[2];
    const float* ap  = (const float*)d_in[3];
    const int*   ep  = (const int*)d_in[4];
    float* out = (float*)d_out;

    k_scores<<<NBN / 8, 256>>>(x, sw, ap);
    k_sort<<<NB, NN>>>();
    dim3 gw((NRES + TR - 1) / TR, NB);
    k_windows<<<gw, 256>>>(x, ep);
    k_chain<<<NB, 512>>>(x, out);
}

// round 6
// speedup vs baseline: 2.5602x; 1.0921x over previous
#include <cuda_runtime.h>
#include <math.h>

#define NB   64
#define NN   512
#define NC   128
#define NFS  16
#define NRES 511
#define NBN  (NB*NN)
#define TR   32
#define TROWS (TR + NFS - 1)   // 47 tile rows

// Scratch (no allocations allowed)
__device__ float g_score[NBN];
__device__ float g_ssrc[NBN];
__device__ float g_sdst[NBN];
__device__ int   g_order[NBN];
__device__ float g_sr[NBN];
__device__ float g_dsrc[NBN];
__device__ float g_ddst[NBN];
__device__ float g_wv[NB*NRES];
__device__ int   g_jumps[NB*NRES];

// -------- Kernel 1: per-node score + attention dots --------
// Warp per node; 2-stage butterfly then SMEM finish (8 shfl/node vs 20).
__global__ void k_scores(const float* __restrict__ x,
                         const float* __restrict__ sw,
                         const float* __restrict__ ap) {
    __shared__ float sp[8][4][8];
    __shared__ float sfin[8][4];
    int t = threadIdx.x, w = t >> 5, lane = t & 31;
    int node = blockIdx.x * 8 + w;

    float4 xv = *(const float4*)(x  + (size_t)node * NC + lane * 4);
    float4 wv = *(const float4*)(sw + lane * 4);
    float4 as = *(const float4*)(ap + lane * 4);
    float4 ad = *(const float4*)(ap + NC + lane * 4);
    float s  = xv.x*wv.x + xv.y*wv.y + xv.z*wv.z + xv.w*wv.w;
    float ps = xv.x*as.x + xv.y*as.y + xv.z*as.z + xv.w*as.w;
    float pd = xv.x*ad.x + xv.y*ad.y + xv.z*ad.z + xv.w*ad.w;
    float wn = wv.x*wv.x + wv.y*wv.y + wv.z*wv.z + wv.w*wv.w;
    #pragma unroll
    for (int o = 16; o >= 8; o >>= 1) {
        s  += __shfl_xor_sync(0xffffffffu, s,  o);
        ps += __shfl_xor_sync(0xffffffffu, ps, o);
        pd += __shfl_xor_sync(0xffffffffu, pd, o);
        wn += __shfl_xor_sync(0xffffffffu, wn, o);
    }
    if (lane < 8) {
        sp[w][0][lane] = s;  sp[w][1][lane] = ps;
        sp[w][2][lane] = pd; sp[w][3][lane] = wn;
    }
    __syncthreads();
    if (t < 32) {
        int nd = t >> 2, v = t & 3;
        const float* q = sp[nd][v];
        sfin[nd][v] = ((q[0]+q[1])+(q[2]+q[3])) + ((q[4]+q[5])+(q[6]+q[7]));
    }
    __syncthreads();
    if (t < 8) {
        int gn = blockIdx.x * 8 + t;
        g_score[gn] = sfin[t][0] / sqrtf(sfin[t][3]);
        g_ssrc[gn]  = sfin[t][1];
        g_sdst[gn]  = sfin[t][2];
    }
}

// -------- Kernel 2: register-resident bitonic sort with u64 keys --------
__global__ void k_sort() {
    __shared__ unsigned long long sk[NN];
    int b = blockIdx.x, t = threadIdx.x;
    float sval = g_score[b * NN + t];
    unsigned u = __float_as_uint(sval);
    u = (u & 0x80000000u) ? ~u : (u | 0x80000000u);
    u = ~u;
    unsigned long long key = ((unsigned long long)u << 32) | (unsigned)t;

    #pragma unroll
    for (int k = 2; k <= NN; k <<= 1) {
        #pragma unroll
        for (int j = k >> 1; j > 0; j >>= 1) {
            unsigned long long other;
            if (j >= 32) {
                __syncthreads();
                sk[t] = key;
                __syncthreads();
                other = sk[t ^ j];
            } else {
                other = __shfl_xor_sync(0xffffffffu, key, j);
            }
            bool takeMin = (((t & j) == 0) == ((t & k) == 0));
            bool less = key < other;
            key = (takeMin == less) ? key : other;
        }
    }

    int idx = (int)(key & 0xffffffffu);
    int gi  = b * NN + idx;
    g_order[b * NN + t] = idx;
    g_sr[b * NN + t]    = tanhf(g_score[gi]);
    g_dsrc[b * NN + t]  = g_ssrc[gi];
    g_ddst[b * NN + t]  = g_sdst[gi];
}

// -------- Kernel 3: banded window, register-xs / streamed-xd --------
__global__ void k_windows(const float* __restrict__ x,
                          const int*   __restrict__ ep) {
    __shared__ __align__(16) float tile[TROWS * NC];    // 24064 B
    __shared__ __align__(16) float sp8[TR * 15 * 8];    // 15360 B
    __shared__ __align__(16) float skk[TR * 15];        // 1920 B
    __shared__ __align__(16) float sddst[48];           // padded to 16B mult
    int b  = blockIdx.y;
    int r0 = blockIdx.x * TR;
    int t = threadIdx.x, w = t >> 5, lane = t & 31;
    const int* ord = g_order + b * NN;

    for (int rr = w; rr < TROWS; rr += 8) {
        int gr  = r0 + rr;
        int grc = gr < NN ? gr : (NN - 1);
        int id  = ord[grc];
        float4 v = *(const float4*)(x + ((size_t)(b * NN + id)) * NC + lane * 4);
        *(float4*)(tile + rr * NC + lane * 4) = v;
    }
    if (t < TROWS) {
        int gr  = r0 + t;
        int grc = gr < NN ? gr : (NN - 1);
        sddst[t] = g_ddst[b * NN + grc];
    }
    __syncthreads();

    // Phase A: warp w owns source rows rbase..rbase+3 (in registers);
    // each dest row read from SMEM exactly once.
    int rbase = w * 4;
    float4 xs0 = *(const float4*)(tile + (rbase + 0) * NC + lane * 4);
    float4 xs1 = *(const float4*)(tile + (rbase + 1) * NC + lane * 4);
    float4 xs2 = *(const float4*)(tile + (rbase + 2) * NC + lane * 4);
    float4 xs3 = *(const float4*)(tile + (rbase + 3) * NC + lane * 4);

    #pragma unroll
    for (int dd = 1; dd <= 18; dd++) {
        float4 xd = *(const float4*)(tile + (rbase + dd) * NC + lane * 4);
        #pragma unroll
        for (int i = 0; i < 4; i++) {
            int j = dd - i;                  // compile-time per (dd,i)
            if (j >= 1 && j <= 15) {
                float4 xs = (i == 0) ? xs0 : (i == 1) ? xs1 : (i == 2) ? xs2 : xs3;
                float dx = xs.x - xd.x, dy = xs.y - xd.y;
                float dz = xs.z - xd.z, dw = xs.w - xd.w;
                float p = dx*dx + dy*dy + dz*dz + dw*dw;
                p += __shfl_xor_sync(0xffffffffu, p, 16);
                p += __shfl_xor_sync(0xffffffffu, p, 8);
                if (lane < 8)
                    sp8[((rbase + i) * 15 + (j - 1)) * 8 + lane] = p;
            }
        }
    }
    __syncthreads();

    // Phase B1: sum 8 partials, kk = exp(-sqrt(d2)/2) - EPS
    for (int i = t; i < TR * 15; i += 256) {
        int rl = i / 15, jm1 = i - rl * 15;
        bool valid = (r0 + rl + jm1 + 1) < NN;
        float4 a  = *(const float4*)(sp8 + i * 8);
        float4 b4 = *(const float4*)(sp8 + i * 8 + 4);
        float d2 = ((a.x + a.y) + (a.z + a.w)) + ((b4.x + b4.y) + (b4.z + b4.w));
        skk[i] = valid ? (expf(-0.5f * sqrtf(d2)) - 1e-20f) : -1e-20f;
    }
    __syncthreads();

    // Phase B2: thread-per-r softmax / max / argmax
    if (t < TR) {
        int r = r0 + t;
        if (r < NRES) {
            int epoch = *ep;
            float tau = (float)(10.0 * exp((double)epoch * -0.046051701859880914));
            float dsr = g_dsrc[b * NN + r];

            float att[16], kk[16];
            kk[0]  = 1.0f;
            att[0] = dsr + sddst[t];
            #pragma unroll
            for (int j = 1; j < NFS; j++) {
                bool valid = (r + j) < NN;
                kk[j]  = skk[t * 15 + (j - 1)];
                att[j] = valid ? (dsr + sddst[t + j]) : -1e9f;
            }
            float m = att[0];
            #pragma unroll
            for (int j = 1; j < NFS; j++) m = fmaxf(m, att[j]);
            float e[16], ssum = 0.0f;
            #pragma unroll
            for (int j = 0; j < NFS; j++) { e[j] = expf((att[j] - m) / tau); ssum += e[j]; }
            float inv = 1.0f / ssum;

            float wrow = -1e9f, best = -3e9f;
            int bj = 1;
            #pragma unroll
            for (int j = 0; j < NFS; j++) {
                bool valid = (r + j) < NN;
                float q  = kk[j] * (e[j] * inv);
                float qm = valid ? q : -1e9f;
                wrow = fmaxf(wrow, qm);
                if (j >= 1 && qm > best) { best = qm; bj = j; }
            }
            g_wv[b * NRES + r]    = wrow * g_sr[b * NN + r];
            g_jumps[b * NRES + r] = bj;
        }
    }
}

// -------- Kernel 4: path-first chain + warp-strided float4 gather --------
__global__ void k_chain(const float* __restrict__ x, float* __restrict__ out) {
    __shared__ float swv[NRES];
    __shared__ int   sj[NRES];
    __shared__ int   sord[NRES];
    __shared__ int   spath[NRES];
    __shared__ float swt[NRES];
    __shared__ int   scount;
    __shared__ __align__(16) float part[16][NC];     // 8 KB
    int b = blockIdx.x, t = threadIdx.x, w = t >> 5, lane = t & 31;  // 512 thr
    if (t < NRES) {
        swv[t]  = g_wv[b * NRES + t];
        sj[t]   = g_jumps[b * NRES + t];
        sord[t] = g_order[b * NN + t];
    }
    __syncthreads();

    if (t == 0) {     // serial pointer-chase in SMEM
        int p = 0, n = 0;
        while (p < NRES) {
            spath[n] = sord[p];
            swt[n]   = swv[p];
            n++;
            p += sj[p];
        }
        scount = n;
    }
    __syncthreads();

    int n = scount;
    const float* xb = x + (size_t)b * NN * NC;
    float ax = 0.f, ay = 0.f, az = 0.f, aw = 0.f;
    #pragma unroll 4
    for (int i = w; i < n; i += 16) {           // warp-strided: high MLP
        float wt = swt[i];
        float4 xr = *(const float4*)(xb + (size_t)spath[i] * NC + lane * 4);
        ax += wt * xr.x; ay += wt * xr.y; az += wt * xr.z; aw += wt * xr.w;
    }
    part[w][lane * 4 + 0] = ax;
    part[w][lane * 4 + 1] = ay;
    part[w][lane * 4 + 2] = az;
    part[w][lane * 4 + 3] = aw;
    __syncthreads();

    if (t < NC) {
        float s = 0.0f;
        #pragma unroll
        for (int w2 = 0; w2 < 16; w2++) s += part[w2][t];
        out[b * NC + t] = s;
    }
}

extern "C" void kernel_launch(void* const* d_in, const int* in_sizes, int n_in,
                              void* d_out, int out_size) {
    const float* x   = (const float*)d_in[0];
    // d_in[1] = edge_index (unused by the reference forward pass)
    const float* sw  = (const float*)d_in[2];
    const float* ap  = (const float*)d_in[3];
    const int*   ep  = (const int*)d_in[4];
    float* out = (float*)d_out;

    k_scores<<<NBN / 8, 256>>>(x, sw, ap);
    k_sort<<<NB, NN>>>();
    dim3 gw((NRES + TR - 1) / TR, NB);
    k_windows<<<gw, 256>>>(x, ep);
    k_chain<<<NB, 512>>>(x, out);
}